// round 2
// baseline (speedup 1.0000x reference)
#include <cuda_runtime.h>
#include <cuda_bf16.h>
#include <math.h>

// Problem constants
#define B_ 2
#define S_ 2048
#define D_ 1024
#define H_ 16
#define DH_ 64
#define M_ (B_ * S_)          // 4096 rows (b*s)

// Scratch (device globals; allocation-free per harness rules)
__device__ float g_q[(size_t)M_ * D_];
__device__ float g_k[(size_t)M_ * D_];
__device__ float g_v[(size_t)M_ * D_];
__device__ float g_att[(size_t)M_ * D_];

// ---------------------------------------------------------------------------
// Core SGEMM tile routine: C[m,n] = sum_k A[m,k] * B[n,k]
// (A: MxK row-major, B: NxK row-major). 128x128 block tile, 8x8 per thread,
// BK=8, 256 threads. M=4096, N=K=1024 -> no bounds checks.
// ---------------------------------------------------------------------------
__device__ __forceinline__ void sgemm_tile(
    const float* __restrict__ A, const float* __restrict__ Bm,
    float* __restrict__ C, int brow, int bcol)
{
    const int N = D_;
    const int K = D_;

    __shared__ float As[8][128];
    __shared__ float Bs[8][128];

    const int tid  = threadIdx.x;
    const int tx   = tid & 15;        // 0..15 -> 8 cols each
    const int ty   = tid >> 4;        // 0..15 -> 8 rows each

    const int lrow = tid >> 1;        // 0..127
    const int lcol = (tid & 1) * 4;   // 0 or 4

    const float* Aptr = A  + (size_t)(brow + lrow) * K + lcol;
    const float* Bptr = Bm + (size_t)(bcol + lrow) * K + lcol;

    float acc[8][8];
#pragma unroll
    for (int i = 0; i < 8; i++)
#pragma unroll
        for (int j = 0; j < 8; j++) acc[i][j] = 0.0f;

    for (int k0 = 0; k0 < K; k0 += 8) {
        float4 a4 = *(const float4*)(Aptr + k0);
        float4 b4 = *(const float4*)(Bptr + k0);
        As[lcol + 0][lrow] = a4.x;
        As[lcol + 1][lrow] = a4.y;
        As[lcol + 2][lrow] = a4.z;
        As[lcol + 3][lrow] = a4.w;
        Bs[lcol + 0][lrow] = b4.x;
        Bs[lcol + 1][lrow] = b4.y;
        Bs[lcol + 2][lrow] = b4.z;
        Bs[lcol + 3][lrow] = b4.w;
        __syncthreads();

#pragma unroll
        for (int k = 0; k < 8; k++) {
            float a[8], bb[8];
#pragma unroll
            for (int i = 0; i < 8; i++) a[i] = As[k][ty * 8 + i];
#pragma unroll
            for (int j = 0; j < 8; j++) bb[j] = Bs[k][tx * 8 + j];
#pragma unroll
            for (int i = 0; i < 8; i++)
#pragma unroll
                for (int j = 0; j < 8; j++)
                    acc[i][j] = fmaf(a[i], bb[j], acc[i][j]);
        }
        __syncthreads();
    }

#pragma unroll
    for (int i = 0; i < 8; i++) {
        float* Crow = C + (size_t)(brow + ty * 8 + i) * N + bcol + tx * 8;
#pragma unroll
        for (int j = 0; j < 8; j += 4) {
            float4 v = make_float4(acc[i][j], acc[i][j + 1],
                                   acc[i][j + 2], acc[i][j + 3]);
            *(float4*)(Crow + j) = v;
        }
    }
}

// ---------------------------------------------------------------------------
// Fused Q/K/V projection: blockIdx.z selects {Wq->g_q, Wk->g_k, Wv->g_v}.
// All three z-slices share A = x -> L2 reuse of x tiles.
// ---------------------------------------------------------------------------
__global__ __launch_bounds__(256) void qkv_proj_kernel(
    const float* __restrict__ x,
    const float* __restrict__ wq,
    const float* __restrict__ wk,
    const float* __restrict__ wv)
{
    const float* w;
    float* dst;
    switch (blockIdx.z) {
        case 0:  w = wq; dst = g_q; break;
        case 1:  w = wk; dst = g_k; break;
        default: w = wv; dst = g_v; break;
    }
    sgemm_tile(x, w, dst, blockIdx.y * 128, blockIdx.x * 128);
}

// Output projection: out = g_att @ Wo^T
__global__ __launch_bounds__(256) void out_proj_kernel(
    const float* __restrict__ wo, float* __restrict__ out)
{
    sgemm_tile(g_att, wo, out, blockIdx.y * 128, blockIdx.x * 128);
}

// ---------------------------------------------------------------------------
// RoPE on g_q and g_k in-place.
// Layout: row = b*S + s, column = h*64 + e. Pairs are (2k, 2k+1) within head.
// inv_freq = theta^(-2k/dh) = 10000^(-k/32)
// ---------------------------------------------------------------------------
__global__ void rope_kernel(const int* __restrict__ pos)
{
    const int PAIRS = M_ * D_ / 2;
    int idx = blockIdx.x * blockDim.x + threadIdx.x;
    if (idx >= PAIRS) return;

    int c2  = idx % (D_ / 2);        // pair index within row; column = 2*c2
    int row = idx / (D_ / 2);        // b*S + s
    int s   = row & (S_ - 1);
    int kk  = c2 & (DH_ / 2 - 1);    // k within head, 0..31

    // theta^(-k/32) = 2^(-k * log2(theta)/32)
    const float l2t_over = 13.287712379549449f / 32.0f;  // log2(10000)/32
    float inv = exp2f(-(float)kk * l2t_over);
    float ang = (float)pos[s] * inv;
    float sn, cs;
    sincosf(ang, &sn, &cs);

    size_t off = (size_t)row * D_ + 2 * c2;
    float qe = g_q[off], qo = g_q[off + 1];
    g_q[off]     = cs * qe - sn * qo;
    g_q[off + 1] = sn * qe + cs * qo;
    float ke = g_k[off], ko = g_k[off + 1];
    g_k[off]     = cs * ke - sn * ko;
    g_k[off + 1] = sn * ke + cs * ko;
}

// ---------------------------------------------------------------------------
// Causal flash attention, fp32.
// Grid: (S/128, H, B). Block: 128 threads, one query row per thread.
// Each thread keeps q[64] (pre-scaled) and o[64] in registers.
// K/V staged in smem in 32-key tiles; inner loop is broadcast-LDS + FMA.
// Online softmax with lazy rescale (only when a new max appears).
// ---------------------------------------------------------------------------
__global__ __launch_bounds__(128) void attn_kernel()
{
    const int b  = blockIdx.z;
    const int h  = blockIdx.y;
    const int q0 = blockIdx.x * 128;
    const int qpos = q0 + threadIdx.x;

    __shared__ float Ks[32][64];
    __shared__ float Vs[32][64];

    const float* Qrow = g_q + ((size_t)(b * S_ + qpos)) * D_ + h * DH_;
    float q[DH_];
#pragma unroll
    for (int e = 0; e < DH_; e++) q[e] = Qrow[e] * 0.125f;  // 1/sqrt(64)

    float o[DH_];
#pragma unroll
    for (int e = 0; e < DH_; e++) o[e] = 0.0f;
    float m = -INFINITY;
    float l = 0.0f;

    const int kend = q0 + 128;  // exclusive; multiple of 32, <= S_

    for (int t0 = 0; t0 < kend; t0 += 32) {
        // cooperative load of 32x64 K and V tiles (512 float4 each)
        for (int i = threadIdx.x; i < 512; i += 128) {
            int r  = i >> 4;
            int c4 = (i & 15) << 2;
            size_t gof = ((size_t)(b * S_ + t0 + r)) * D_ + h * DH_ + c4;
            *(float4*)&Ks[r][c4] = *(const float4*)&g_k[gof];
            *(float4*)&Vs[r][c4] = *(const float4*)&g_v[gof];
        }
        __syncthreads();

        int jmax = qpos - t0 + 1;
        if (jmax > 32) jmax = 32;
        for (int j = 0; j < jmax; j++) {
            float s = 0.0f;
#pragma unroll
            for (int e = 0; e < DH_; e++) s = fmaf(q[e], Ks[j][e], s);
            if (s > m) {
                float alpha = __expf(m - s);  // exp(-inf)=0 on first key
                l *= alpha;
#pragma unroll
                for (int e = 0; e < DH_; e++) o[e] *= alpha;
                m = s;
            }
            float p = __expf(s - m);
            l += p;
#pragma unroll
            for (int e = 0; e < DH_; e++) o[e] = fmaf(p, Vs[j][e], o[e]);
        }
        __syncthreads();
    }

    float inv_l = 1.0f / l;
    float* Orow = g_att + ((size_t)(b * S_ + qpos)) * D_ + h * DH_;
#pragma unroll
    for (int e = 0; e < DH_; e++) Orow[e] = o[e] * inv_l;
}

// ---------------------------------------------------------------------------
// kernel_launch — launches ONLY (no other runtime API calls; graph-capture safe)
// Inputs (metadata order): x, q_proj_weight, k_proj_weight, v_proj_weight,
//                          o_proj_weight, token_positions
// ---------------------------------------------------------------------------
extern "C" void kernel_launch(void* const* d_in, const int* in_sizes, int n_in,
                              void* d_out, int out_size)
{
    const float* x   = (const float*)d_in[0];
    const float* wq  = (const float*)d_in[1];
    const float* wk  = (const float*)d_in[2];
    const float* wv  = (const float*)d_in[3];
    const float* wo  = (const float*)d_in[4];
    const int*   pos = (const int*)d_in[5];
    float* out = (float*)d_out;

    dim3 qkvGrid(D_ / 128, M_ / 128, 3);   // (8, 32, 3)
    qkv_proj_kernel<<<qkvGrid, 256>>>(x, wq, wk, wv);

    const int PAIRS = M_ * D_ / 2;
    rope_kernel<<<(PAIRS + 255) / 256, 256>>>(pos);

    dim3 attnGrid(S_ / 128, H_, B_);
    attn_kernel<<<attnGrid, 128>>>();

    dim3 gemmGrid(D_ / 128, M_ / 128);     // (8, 32)
    out_proj_kernel<<<gemmGrid, 256>>>(wo, out);
}

// round 3
// speedup vs baseline: 1.5463x; 1.5463x over previous
#include <cuda_runtime.h>
#include <cuda_bf16.h>
#include <math.h>
#include <stdint.h>

// Problem constants
#define B_ 2
#define S_ 2048
#define D_ 1024
#define H_ 16
#define DH_ 64
#define M_ (B_ * S_)          // 4096 rows (b*s)

// Scratch (device globals; allocation-free per harness rules)
__device__ float g_q[(size_t)M_ * D_];
__device__ float g_k[(size_t)M_ * D_];
__device__ float g_v[(size_t)M_ * D_];
__device__ float g_att[(size_t)M_ * D_];

// ---------------------------------------------------------------------------
// tf32 helpers
// ---------------------------------------------------------------------------
__device__ __forceinline__ uint32_t f2tf32(float x) {
    uint32_t y;
    asm("cvt.rna.tf32.f32 %0, %1;" : "=r"(y) : "f"(x));
    return y;
}

__device__ __forceinline__ void mma_tf32(float c[4],
                                         uint32_t a0, uint32_t a1,
                                         uint32_t a2, uint32_t a3,
                                         uint32_t b0, uint32_t b1) {
    asm volatile(
        "mma.sync.aligned.m16n8k8.row.col.f32.tf32.tf32.f32 "
        "{%0,%1,%2,%3}, {%4,%5,%6,%7}, {%8,%9}, {%0,%1,%2,%3};\n"
        : "+f"(c[0]), "+f"(c[1]), "+f"(c[2]), "+f"(c[3])
        : "r"(a0), "r"(a1), "r"(a2), "r"(a3), "r"(b0), "r"(b1));
}

// ---------------------------------------------------------------------------
// tf32 tensor-core GEMM tile: C[m,n] = sum_k A[m,k] * B[n,k]
// A: MxK row-major fp32, B: NxK row-major fp32 (i.e. C = A @ B^T).
// Block: 128x128 tile, 256 threads = 8 warps (2 m-warps x 4 n-warps),
// warp tile 64x32, BK=32. fp32 -> tf32 (rna) at smem store.
// M=4096, N=K=1024 -> no bounds checks.
// ---------------------------------------------------------------------------
#define BK_ 32
#define SPAD_ 36   // smem row stride in floats (32 + 4 pad)

__device__ __forceinline__ void gemm_tf32_tile(
    const float* __restrict__ A, const float* __restrict__ Bm,
    float* __restrict__ C, int brow, int bcol)
{
    const int K = D_;
    const int N = D_;

    __shared__ uint32_t As[128 * SPAD_];
    __shared__ uint32_t Bs[128 * SPAD_];

    const int tid = threadIdx.x;
    const int wid = tid >> 5;
    const int lane = tid & 31;
    const int gid = lane >> 2;      // groupID 0..7
    const int tig = lane & 3;       // thread-in-group 0..3

    const int wm = wid >> 2;        // 0..1  (m-warp)
    const int wn = wid & 3;         // 0..3  (n-warp)

    float acc[4][4][4];             // [mt][nt][4]
#pragma unroll
    for (int mt = 0; mt < 4; mt++)
#pragma unroll
        for (int nt = 0; nt < 4; nt++)
#pragma unroll
            for (int r = 0; r < 4; r++) acc[mt][nt][r] = 0.0f;

    for (int k0 = 0; k0 < K; k0 += BK_) {
        // cooperative load: 128 rows x 32 cols each of A and B = 1024 float4
#pragma unroll
        for (int i = 0; i < 4; i++) {
            int li = i * 256 + tid;
            int row = li >> 3;
            int c4 = (li & 7) << 2;
            float4 a4 = *(const float4*)(A + (size_t)(brow + row) * K + k0 + c4);
            float4 b4 = *(const float4*)(Bm + (size_t)(bcol + row) * K + k0 + c4);
            uint32_t* ap = &As[row * SPAD_ + c4];
            ap[0] = f2tf32(a4.x); ap[1] = f2tf32(a4.y);
            ap[2] = f2tf32(a4.z); ap[3] = f2tf32(a4.w);
            uint32_t* bp = &Bs[row * SPAD_ + c4];
            bp[0] = f2tf32(b4.x); bp[1] = f2tf32(b4.y);
            bp[2] = f2tf32(b4.z); bp[3] = f2tf32(b4.w);
        }
        __syncthreads();

#pragma unroll
        for (int ka = 0; ka < 4; ka++) {
            const int kc = ka * 8 + tig;
            uint32_t af[4][4];
#pragma unroll
            for (int mt = 0; mt < 4; mt++) {
                int r0 = wm * 64 + mt * 16 + gid;
                af[mt][0] = As[r0 * SPAD_ + kc];
                af[mt][1] = As[(r0 + 8) * SPAD_ + kc];
                af[mt][2] = As[r0 * SPAD_ + kc + 4];
                af[mt][3] = As[(r0 + 8) * SPAD_ + kc + 4];
            }
            uint32_t bf[4][2];
#pragma unroll
            for (int nt = 0; nt < 4; nt++) {
                int rn = wn * 32 + nt * 8 + gid;
                bf[nt][0] = Bs[rn * SPAD_ + kc];
                bf[nt][1] = Bs[rn * SPAD_ + kc + 4];
            }
#pragma unroll
            for (int mt = 0; mt < 4; mt++)
#pragma unroll
                for (int nt = 0; nt < 4; nt++)
                    mma_tf32(acc[mt][nt],
                             af[mt][0], af[mt][1], af[mt][2], af[mt][3],
                             bf[nt][0], bf[nt][1]);
        }
        __syncthreads();
    }

    // epilogue: c0,c1 -> (row, col..col+1); c2,c3 -> (row+8, col..col+1)
#pragma unroll
    for (int mt = 0; mt < 4; mt++) {
        int row = brow + wm * 64 + mt * 16 + gid;
#pragma unroll
        for (int nt = 0; nt < 4; nt++) {
            int col = bcol + wn * 32 + nt * 8 + tig * 2;
            float2 v01 = make_float2(acc[mt][nt][0], acc[mt][nt][1]);
            float2 v23 = make_float2(acc[mt][nt][2], acc[mt][nt][3]);
            *(float2*)(C + (size_t)row * N + col) = v01;
            *(float2*)(C + (size_t)(row + 8) * N + col) = v23;
        }
    }
}

// ---------------------------------------------------------------------------
// Fused Q/K/V projection: blockIdx.z selects {Wq->g_q, Wk->g_k, Wv->g_v}.
// ---------------------------------------------------------------------------
__global__ __launch_bounds__(256) void qkv_proj_kernel(
    const float* __restrict__ x,
    const float* __restrict__ wq,
    const float* __restrict__ wk,
    const float* __restrict__ wv)
{
    const float* w;
    float* dst;
    switch (blockIdx.z) {
        case 0:  w = wq; dst = g_q; break;
        case 1:  w = wk; dst = g_k; break;
        default: w = wv; dst = g_v; break;
    }
    gemm_tf32_tile(x, w, dst, blockIdx.y * 128, blockIdx.x * 128);
}

// Output projection: out = g_att @ Wo^T
__global__ __launch_bounds__(256) void out_proj_kernel(
    const float* __restrict__ wo, float* __restrict__ out)
{
    gemm_tf32_tile(g_att, wo, out, blockIdx.y * 128, blockIdx.x * 128);
}

// ---------------------------------------------------------------------------
// RoPE on g_q and g_k in-place.
// ---------------------------------------------------------------------------
__global__ void rope_kernel(const int* __restrict__ pos)
{
    const int PAIRS = M_ * D_ / 2;
    int idx = blockIdx.x * blockDim.x + threadIdx.x;
    if (idx >= PAIRS) return;

    int c2  = idx % (D_ / 2);        // pair index within row; column = 2*c2
    int row = idx / (D_ / 2);        // b*S + s
    int s   = row & (S_ - 1);
    int kk  = c2 & (DH_ / 2 - 1);    // k within head, 0..31

    const float l2t_over = 13.287712379549449f / 32.0f;  // log2(10000)/32
    float inv = exp2f(-(float)kk * l2t_over);
    float ang = (float)pos[s] * inv;
    float sn, cs;
    sincosf(ang, &sn, &cs);

    size_t off = (size_t)row * D_ + 2 * c2;
    float qe = g_q[off], qo = g_q[off + 1];
    g_q[off]     = cs * qe - sn * qo;
    g_q[off + 1] = sn * qe + cs * qo;
    float ke = g_k[off], ko = g_k[off + 1];
    g_k[off]     = cs * ke - sn * ko;
    g_k[off + 1] = sn * ke + cs * ko;
}

// ---------------------------------------------------------------------------
// Causal flash attention, fp32 (unchanged from passing R2 version).
// ---------------------------------------------------------------------------
__global__ __launch_bounds__(128) void attn_kernel()
{
    const int b  = blockIdx.z;
    const int h  = blockIdx.y;
    const int q0 = blockIdx.x * 128;
    const int qpos = q0 + threadIdx.x;

    __shared__ float Ks[32][64];
    __shared__ float Vs[32][64];

    const float* Qrow = g_q + ((size_t)(b * S_ + qpos)) * D_ + h * DH_;
    float q[DH_];
#pragma unroll
    for (int e = 0; e < DH_; e++) q[e] = Qrow[e] * 0.125f;  // 1/sqrt(64)

    float o[DH_];
#pragma unroll
    for (int e = 0; e < DH_; e++) o[e] = 0.0f;
    float m = -INFINITY;
    float l = 0.0f;

    const int kend = q0 + 128;  // exclusive; multiple of 32, <= S_

    for (int t0 = 0; t0 < kend; t0 += 32) {
        for (int i = threadIdx.x; i < 512; i += 128) {
            int r  = i >> 4;
            int c4 = (i & 15) << 2;
            size_t gof = ((size_t)(b * S_ + t0 + r)) * D_ + h * DH_ + c4;
            *(float4*)&Ks[r][c4] = *(const float4*)&g_k[gof];
            *(float4*)&Vs[r][c4] = *(const float4*)&g_v[gof];
        }
        __syncthreads();

        int jmax = qpos - t0 + 1;
        if (jmax > 32) jmax = 32;
        for (int j = 0; j < jmax; j++) {
            float s = 0.0f;
#pragma unroll
            for (int e = 0; e < DH_; e++) s = fmaf(q[e], Ks[j][e], s);
            if (s > m) {
                float alpha = __expf(m - s);
                l *= alpha;
#pragma unroll
                for (int e = 0; e < DH_; e++) o[e] *= alpha;
                m = s;
            }
            float p = __expf(s - m);
            l += p;
#pragma unroll
            for (int e = 0; e < DH_; e++) o[e] = fmaf(p, Vs[j][e], o[e]);
        }
        __syncthreads();
    }

    float inv_l = 1.0f / l;
    float* Orow = g_att + ((size_t)(b * S_ + qpos)) * D_ + h * DH_;
#pragma unroll
    for (int e = 0; e < DH_; e++) Orow[e] = o[e] * inv_l;
}

// ---------------------------------------------------------------------------
// kernel_launch — launches ONLY (graph-capture safe)
// Inputs: x, q_proj_weight, k_proj_weight, v_proj_weight, o_proj_weight,
//         token_positions
// ---------------------------------------------------------------------------
extern "C" void kernel_launch(void* const* d_in, const int* in_sizes, int n_in,
                              void* d_out, int out_size)
{
    const float* x   = (const float*)d_in[0];
    const float* wq  = (const float*)d_in[1];
    const float* wk  = (const float*)d_in[2];
    const float* wv  = (const float*)d_in[3];
    const float* wo  = (const float*)d_in[4];
    const int*   pos = (const int*)d_in[5];
    float* out = (float*)d_out;

    dim3 qkvGrid(D_ / 128, M_ / 128, 3);   // (8, 32, 3)
    qkv_proj_kernel<<<qkvGrid, 256>>>(x, wq, wk, wv);

    const int PAIRS = M_ * D_ / 2;
    rope_kernel<<<(PAIRS + 255) / 256, 256>>>(pos);

    dim3 attnGrid(S_ / 128, H_, B_);
    attn_kernel<<<attnGrid, 128>>>();

    dim3 gemmGrid(D_ / 128, M_ / 128);     // (8, 32)
    out_proj_kernel<<<gemmGrid, 256>>>(wo, out);
}

// round 4
// speedup vs baseline: 1.7439x; 1.1278x over previous
#include <cuda_runtime.h>
#include <cuda_bf16.h>
#include <math.h>
#include <stdint.h>

// Problem constants
#define B_ 2
#define S_ 2048
#define D_ 1024
#define H_ 16
#define DH_ 64
#define M_ (B_ * S_)          // 4096 rows (b*s)

// Scratch (device globals; allocation-free per harness rules)
__device__ float g_q[(size_t)M_ * D_];
__device__ float g_k[(size_t)M_ * D_];
__device__ float g_v[(size_t)M_ * D_];
__device__ float g_att[(size_t)M_ * D_];

// ---------------------------------------------------------------------------
// tf32 helpers
// ---------------------------------------------------------------------------
__device__ __forceinline__ uint32_t f2tf32(float x) {
    uint32_t y;
    asm("cvt.rna.tf32.f32 %0, %1;" : "=r"(y) : "f"(x));
    return y;
}

__device__ __forceinline__ void mma_tf32(float c[4],
                                         uint32_t a0, uint32_t a1,
                                         uint32_t a2, uint32_t a3,
                                         uint32_t b0, uint32_t b1) {
    asm volatile(
        "mma.sync.aligned.m16n8k8.row.col.f32.tf32.tf32.f32 "
        "{%0,%1,%2,%3}, {%4,%5,%6,%7}, {%8,%9}, {%0,%1,%2,%3};\n"
        : "+f"(c[0]), "+f"(c[1]), "+f"(c[2]), "+f"(c[3])
        : "r"(a0), "r"(a1), "r"(a2), "r"(a3), "r"(b0), "r"(b1));
}

// ---------------------------------------------------------------------------
// 3xTF32 GEMM tile: C[m,n] = sum_k A[m,k] * B[n,k]  (near-fp32 accuracy)
// A: MxK row-major fp32, B: NxK row-major fp32 (C = A @ B^T).
// Block 128x128, 256 threads = 8 warps (2m x 4n), warp tile 64x32, BK=16.
// Each operand split x = hi + lo (tf32 pair); C = hh + hl + lh.
// ---------------------------------------------------------------------------
#define PBK_ 16
#define PSTR_ 20   // smem row stride (words)

__device__ __forceinline__ void gemm3x_tile(
    const float* __restrict__ A, const float* __restrict__ Bm,
    float* __restrict__ C, int brow, int bcol)
{
    const int K = D_;
    const int N = D_;

    __shared__ uint32_t Ah[128 * PSTR_];
    __shared__ uint32_t Al[128 * PSTR_];
    __shared__ uint32_t Bh[128 * PSTR_];
    __shared__ uint32_t Bl[128 * PSTR_];

    const int tid  = threadIdx.x;
    const int wid  = tid >> 5;
    const int lane = tid & 31;
    const int gid  = lane >> 2;
    const int tig  = lane & 3;
    const int wm   = wid >> 2;   // 0..1
    const int wn   = wid & 3;    // 0..3

    const int lrow = tid >> 1;          // 0..127
    const int lc8  = (tid & 1) * 8;     // 0 or 8

    const float* Ap = A  + (size_t)(brow + lrow) * K + lc8;
    const float* Bp = Bm + (size_t)(bcol + lrow) * K + lc8;

    float acc[4][4][4];
#pragma unroll
    for (int mt = 0; mt < 4; mt++)
#pragma unroll
        for (int nt = 0; nt < 4; nt++)
#pragma unroll
            for (int r = 0; r < 4; r++) acc[mt][nt][r] = 0.0f;

    // prefetch first tile into regs
    float4 av0 = *(const float4*)(Ap);
    float4 av1 = *(const float4*)(Ap + 4);
    float4 bv0 = *(const float4*)(Bp);
    float4 bv1 = *(const float4*)(Bp + 4);

    for (int k0 = 0; k0 < K; k0 += PBK_) {
        // split current tile into hi/lo and store
        {
            float va[8] = {av0.x, av0.y, av0.z, av0.w, av1.x, av1.y, av1.z, av1.w};
            float vb[8] = {bv0.x, bv0.y, bv0.z, bv0.w, bv1.x, bv1.y, bv1.z, bv1.w};
            uint32_t ah[8], al[8], bh[8], bl[8];
#pragma unroll
            for (int i = 0; i < 8; i++) {
                ah[i] = f2tf32(va[i]);
                al[i] = f2tf32(va[i] - __uint_as_float(ah[i]));
                bh[i] = f2tf32(vb[i]);
                bl[i] = f2tf32(vb[i] - __uint_as_float(bh[i]));
            }
            int base = lrow * PSTR_ + lc8;
            *(uint4*)&Ah[base]     = make_uint4(ah[0], ah[1], ah[2], ah[3]);
            *(uint4*)&Ah[base + 4] = make_uint4(ah[4], ah[5], ah[6], ah[7]);
            *(uint4*)&Al[base]     = make_uint4(al[0], al[1], al[2], al[3]);
            *(uint4*)&Al[base + 4] = make_uint4(al[4], al[5], al[6], al[7]);
            *(uint4*)&Bh[base]     = make_uint4(bh[0], bh[1], bh[2], bh[3]);
            *(uint4*)&Bh[base + 4] = make_uint4(bh[4], bh[5], bh[6], bh[7]);
            *(uint4*)&Bl[base]     = make_uint4(bl[0], bl[1], bl[2], bl[3]);
            *(uint4*)&Bl[base + 4] = make_uint4(bl[4], bl[5], bl[6], bl[7]);
        }
        __syncthreads();

        // prefetch next tile
        if (k0 + PBK_ < K) {
            av0 = *(const float4*)(Ap + k0 + PBK_);
            av1 = *(const float4*)(Ap + k0 + PBK_ + 4);
            bv0 = *(const float4*)(Bp + k0 + PBK_);
            bv1 = *(const float4*)(Bp + k0 + PBK_ + 4);
        }

#pragma unroll
        for (int ka = 0; ka < 2; ka++) {
            const int kc = ka * 8 + tig;
            uint32_t afh[4][4], afl[4][4];
#pragma unroll
            for (int mt = 0; mt < 4; mt++) {
                int r0 = wm * 64 + mt * 16 + gid;
                afh[mt][0] = Ah[r0 * PSTR_ + kc];
                afh[mt][1] = Ah[(r0 + 8) * PSTR_ + kc];
                afh[mt][2] = Ah[r0 * PSTR_ + kc + 4];
                afh[mt][3] = Ah[(r0 + 8) * PSTR_ + kc + 4];
                afl[mt][0] = Al[r0 * PSTR_ + kc];
                afl[mt][1] = Al[(r0 + 8) * PSTR_ + kc];
                afl[mt][2] = Al[r0 * PSTR_ + kc + 4];
                afl[mt][3] = Al[(r0 + 8) * PSTR_ + kc + 4];
            }
            uint32_t bfh[4][2], bfl[4][2];
#pragma unroll
            for (int nt = 0; nt < 4; nt++) {
                int rn = wn * 32 + nt * 8 + gid;
                bfh[nt][0] = Bh[rn * PSTR_ + kc];
                bfh[nt][1] = Bh[rn * PSTR_ + kc + 4];
                bfl[nt][0] = Bl[rn * PSTR_ + kc];
                bfl[nt][1] = Bl[rn * PSTR_ + kc + 4];
            }
#pragma unroll
            for (int mt = 0; mt < 4; mt++)
#pragma unroll
                for (int nt = 0; nt < 4; nt++) {
                    mma_tf32(acc[mt][nt], afh[mt][0], afh[mt][1], afh[mt][2], afh[mt][3],
                             bfh[nt][0], bfh[nt][1]);
                    mma_tf32(acc[mt][nt], afh[mt][0], afh[mt][1], afh[mt][2], afh[mt][3],
                             bfl[nt][0], bfl[nt][1]);
                    mma_tf32(acc[mt][nt], afl[mt][0], afl[mt][1], afl[mt][2], afl[mt][3],
                             bfh[nt][0], bfh[nt][1]);
                }
        }
        __syncthreads();
    }

#pragma unroll
    for (int mt = 0; mt < 4; mt++) {
        int row = brow + wm * 64 + mt * 16 + gid;
#pragma unroll
        for (int nt = 0; nt < 4; nt++) {
            int col = bcol + wn * 32 + nt * 8 + tig * 2;
            *(float2*)(C + (size_t)row * N + col) =
                make_float2(acc[mt][nt][0], acc[mt][nt][1]);
            *(float2*)(C + (size_t)(row + 8) * N + col) =
                make_float2(acc[mt][nt][2], acc[mt][nt][3]);
        }
    }
}

__global__ __launch_bounds__(256) void qkv_proj_kernel(
    const float* __restrict__ x,
    const float* __restrict__ wq,
    const float* __restrict__ wk,
    const float* __restrict__ wv)
{
    const float* w;
    float* dst;
    switch (blockIdx.z) {
        case 0:  w = wq; dst = g_q; break;
        case 1:  w = wk; dst = g_k; break;
        default: w = wv; dst = g_v; break;
    }
    gemm3x_tile(x, w, dst, blockIdx.y * 128, blockIdx.x * 128);
}

__global__ __launch_bounds__(256) void out_proj_kernel(
    const float* __restrict__ wo, float* __restrict__ out)
{
    gemm3x_tile(g_att, wo, out, blockIdx.y * 128, blockIdx.x * 128);
}

// ---------------------------------------------------------------------------
// RoPE on g_q and g_k in-place.
// ---------------------------------------------------------------------------
__global__ void rope_kernel(const int* __restrict__ pos)
{
    const int PAIRS = M_ * D_ / 2;
    int idx = blockIdx.x * blockDim.x + threadIdx.x;
    if (idx >= PAIRS) return;

    int c2  = idx % (D_ / 2);
    int row = idx / (D_ / 2);
    int s   = row & (S_ - 1);
    int kk  = c2 & (DH_ / 2 - 1);

    const float l2t_over = 13.287712379549449f / 32.0f;  // log2(10000)/32
    float inv = exp2f(-(float)kk * l2t_over);
    float ang = (float)pos[s] * inv;
    float sn, cs;
    sincosf(ang, &sn, &cs);

    size_t off = (size_t)row * D_ + 2 * c2;
    float qe = g_q[off], qo = g_q[off + 1];
    g_q[off]     = cs * qe - sn * qo;
    g_q[off + 1] = sn * qe + cs * qo;
    float ke = g_k[off], ko = g_k[off + 1];
    g_k[off]     = cs * ke - sn * ko;
    g_k[off + 1] = sn * ke + cs * ko;
}

// ---------------------------------------------------------------------------
// Causal flash attention with tf32 mma.
// Grid (S/128, H, B), block 256 (8 warps). Warp w owns q-rows [16w,16w+16).
// K-tile = 32 keys. Kt stored [dim][key^swz] (swz = 8*(dim&3)), stride 32.
// Vs stored [key][dim], stride 72. P per-warp smem round-trip, stride 36.
// ---------------------------------------------------------------------------
#define PADV 72
#define PADP 36

__global__ __launch_bounds__(256) void attn_mma_kernel()
{
    __shared__ uint32_t Kt[64 * 32];          // 8 KB
    __shared__ uint32_t Vs[32 * PADV];        // 9 KB
    __shared__ uint32_t Ps[8][16 * PADP];     // 18 KB

    const int b   = blockIdx.z;
    const int h   = blockIdx.y;
    const int q0  = blockIdx.x * 128;
    const int tid = threadIdx.x;
    const int w   = tid >> 5;
    const int lane = tid & 31;
    const int gid = lane >> 2;
    const int tig = lane & 3;

    const int r0 = q0 + 16 * w + gid;       // first owned row (second = r0+8)

    // Q fragments (scaled by 1/sqrt(dh) = 0.125, exact power of 2)
    uint32_t qf[8][4];
    {
        const float* Qb = g_q + ((size_t)(b * S_) + r0) * D_ + h * DH_;
#pragma unroll
        for (int kst = 0; kst < 8; kst++) {
            qf[kst][0] = f2tf32(Qb[kst * 8 + tig] * 0.125f);
            qf[kst][1] = f2tf32(Qb[8 * D_ + kst * 8 + tig] * 0.125f);
            qf[kst][2] = f2tf32(Qb[kst * 8 + tig + 4] * 0.125f);
            qf[kst][3] = f2tf32(Qb[8 * D_ + kst * 8 + tig + 4] * 0.125f);
        }
    }

    float o[8][4];
#pragma unroll
    for (int nb = 0; nb < 8; nb++)
#pragma unroll
        for (int r = 0; r < 4; r++) o[nb][r] = 0.0f;
    float m0 = -1e30f, m1 = -1e30f, l0 = 0.0f, l1 = 0.0f;

    const int ntiles  = (q0 + 128) / 32;
    const int wminrow = q0 + 16 * w;
    const int wmaxrow = wminrow + 15;

    for (int t = 0; t < ntiles; t++) {
        const int t0 = t * 32;

        // ---- load K tile transposed+swizzled: warp w covers dims [8w,8w+8) ----
        {
            const float* Kp = g_k + ((size_t)(b * S_) + t0 + lane) * D_ + h * DH_ + w * 8;
            float4 ka = *(const float4*)Kp;
            float4 kb = *(const float4*)(Kp + 4);
            float kv[8] = {ka.x, ka.y, ka.z, ka.w, kb.x, kb.y, kb.z, kb.w};
#pragma unroll
            for (int i = 0; i < 8; i++) {
                int d = w * 8 + i;
                Kt[d * 32 + (lane ^ (8 * (d & 3)))] = f2tf32(kv[i]);
            }
        }
        // ---- load V tile natural ----
        {
            int key  = tid >> 3;
            int part = tid & 7;
            const float* Vp = g_v + ((size_t)(b * S_) + t0 + key) * D_ + h * DH_ + part * 8;
            float4 va = *(const float4*)Vp;
            float4 vb = *(const float4*)(Vp + 4);
            *(uint4*)&Vs[key * PADV + part * 8] =
                make_uint4(f2tf32(va.x), f2tf32(va.y), f2tf32(va.z), f2tf32(va.w));
            *(uint4*)&Vs[key * PADV + part * 8 + 4] =
                make_uint4(f2tf32(vb.x), f2tf32(vb.y), f2tf32(vb.z), f2tf32(vb.w));
        }
        __syncthreads();

        if (t0 <= wmaxrow) {   // otherwise tile fully masked for this warp
            // ---- S = Q K^T (16 x 32 per warp) ----
            float s[4][4];
#pragma unroll
            for (int nb = 0; nb < 4; nb++)
#pragma unroll
                for (int r = 0; r < 4; r++) s[nb][r] = 0.0f;

#pragma unroll
            for (int kst = 0; kst < 8; kst++) {
#pragma unroll
                for (int nb = 0; nb < 4; nb++) {
                    uint32_t b0 = Kt[(kst * 8 + tig) * 32 + ((nb * 8 + gid) ^ (8 * tig))];
                    uint32_t b1 = Kt[(kst * 8 + tig + 4) * 32 + ((nb * 8 + gid) ^ (8 * tig))];
                    mma_tf32(s[nb], qf[kst][0], qf[kst][1], qf[kst][2], qf[kst][3], b0, b1);
                }
            }

            // ---- causal mask ----
            if (t0 + 31 > wminrow) {
#pragma unroll
                for (int nb = 0; nb < 4; nb++) {
                    int key = t0 + nb * 8 + 2 * tig;
                    if (key     > r0)     s[nb][0] = -1e30f;
                    if (key + 1 > r0)     s[nb][1] = -1e30f;
                    if (key     > r0 + 8) s[nb][2] = -1e30f;
                    if (key + 1 > r0 + 8) s[nb][3] = -1e30f;
                }
            }

            // ---- online softmax ----
            float mx0 = -1e30f, mx1 = -1e30f;
#pragma unroll
            for (int nb = 0; nb < 4; nb++) {
                mx0 = fmaxf(mx0, fmaxf(s[nb][0], s[nb][1]));
                mx1 = fmaxf(mx1, fmaxf(s[nb][2], s[nb][3]));
            }
            mx0 = fmaxf(mx0, __shfl_xor_sync(0xffffffffu, mx0, 1));
            mx0 = fmaxf(mx0, __shfl_xor_sync(0xffffffffu, mx0, 2));
            mx1 = fmaxf(mx1, __shfl_xor_sync(0xffffffffu, mx1, 1));
            mx1 = fmaxf(mx1, __shfl_xor_sync(0xffffffffu, mx1, 2));

            float mn0 = fmaxf(m0, mx0);
            float mn1 = fmaxf(m1, mx1);
            float a0 = __expf(m0 - mn0);
            float a1 = __expf(m1 - mn1);

            float ps0 = 0.0f, ps1 = 0.0f;
            uint32_t pt[4][4];
#pragma unroll
            for (int nb = 0; nb < 4; nb++) {
                float p0 = __expf(s[nb][0] - mn0);
                float p1 = __expf(s[nb][1] - mn0);
                float p2 = __expf(s[nb][2] - mn1);
                float p3 = __expf(s[nb][3] - mn1);
                ps0 += p0 + p1;
                ps1 += p2 + p3;
                pt[nb][0] = f2tf32(p0);
                pt[nb][1] = f2tf32(p1);
                pt[nb][2] = f2tf32(p2);
                pt[nb][3] = f2tf32(p3);
            }
            ps0 += __shfl_xor_sync(0xffffffffu, ps0, 1);
            ps0 += __shfl_xor_sync(0xffffffffu, ps0, 2);
            ps1 += __shfl_xor_sync(0xffffffffu, ps1, 1);
            ps1 += __shfl_xor_sync(0xffffffffu, ps1, 2);

            l0 = l0 * a0 + ps0;
            l1 = l1 * a1 + ps1;
            m0 = mn0;
            m1 = mn1;

#pragma unroll
            for (int nb = 0; nb < 8; nb++) {
                o[nb][0] *= a0;
                o[nb][1] *= a0;
                o[nb][2] *= a1;
                o[nb][3] *= a1;
            }

            // ---- P -> per-warp smem (A-fragment layout conversion) ----
            uint32_t* pw = &Ps[w][0];
#pragma unroll
            for (int nb = 0; nb < 4; nb++) {
                *(uint2*)&pw[gid * PADP + nb * 8 + 2 * tig] =
                    make_uint2(pt[nb][0], pt[nb][1]);
                *(uint2*)&pw[(gid + 8) * PADP + nb * 8 + 2 * tig] =
                    make_uint2(pt[nb][2], pt[nb][3]);
            }
            __syncwarp();

            // ---- O += P V ----
#pragma unroll
            for (int kst = 0; kst < 4; kst++) {
                uint32_t pa0 = pw[gid * PADP + kst * 8 + tig];
                uint32_t pa1 = pw[(gid + 8) * PADP + kst * 8 + tig];
                uint32_t pa2 = pw[gid * PADP + kst * 8 + tig + 4];
                uint32_t pa3 = pw[(gid + 8) * PADP + kst * 8 + tig + 4];
#pragma unroll
                for (int nb = 0; nb < 8; nb++) {
                    uint32_t b0 = Vs[(kst * 8 + tig) * PADV + nb * 8 + gid];
                    uint32_t b1 = Vs[(kst * 8 + tig + 4) * PADV + nb * 8 + gid];
                    mma_tf32(o[nb], pa0, pa1, pa2, pa3, b0, b1);
                }
            }
            __syncwarp();
        }
        __syncthreads();
    }

    // ---- epilogue ----
    float inv0 = 1.0f / l0;
    float inv1 = 1.0f / l1;
    float* Ob = g_att + ((size_t)(b * S_) + r0) * D_ + h * DH_;
#pragma unroll
    for (int nb = 0; nb < 8; nb++) {
        *(float2*)&Ob[nb * 8 + 2 * tig] =
            make_float2(o[nb][0] * inv0, o[nb][1] * inv0);
        *(float2*)&Ob[8 * D_ + nb * 8 + 2 * tig] =
            make_float2(o[nb][2] * inv1, o[nb][3] * inv1);
    }
}

// ---------------------------------------------------------------------------
// kernel_launch — launches ONLY (graph-capture safe)
// Inputs: x, q_proj_weight, k_proj_weight, v_proj_weight, o_proj_weight,
//         token_positions
// ---------------------------------------------------------------------------
extern "C" void kernel_launch(void* const* d_in, const int* in_sizes, int n_in,
                              void* d_out, int out_size)
{
    const float* x   = (const float*)d_in[0];
    const float* wq  = (const float*)d_in[1];
    const float* wk  = (const float*)d_in[2];
    const float* wv  = (const float*)d_in[3];
    const float* wo  = (const float*)d_in[4];
    const int*   pos = (const int*)d_in[5];
    float* out = (float*)d_out;

    dim3 qkvGrid(D_ / 128, M_ / 128, 3);   // (8, 32, 3)
    qkv_proj_kernel<<<qkvGrid, 256>>>(x, wq, wk, wv);

    const int PAIRS = M_ * D_ / 2;
    rope_kernel<<<(PAIRS + 255) / 256, 256>>>(pos);

    dim3 attnGrid(S_ / 128, H_, B_);       // (16, 16, 2)
    attn_mma_kernel<<<attnGrid, 256>>>();

    dim3 gemmGrid(D_ / 128, M_ / 128);     // (8, 32)
    out_proj_kernel<<<gemmGrid, 256>>>(wo, out);
}

// round 6
// speedup vs baseline: 3.3406x; 1.9157x over previous
#include <cuda_runtime.h>
#include <cuda_bf16.h>
#include <math.h>
#include <stdint.h>

// Problem constants
#define B_ 2
#define S_ 2048
#define D_ 1024
#define H_ 16
#define DH_ 64
#define M_ (B_ * S_)          // 4096 rows (b*s)

// Scratch (device globals; allocation-free per harness rules)
__device__ float g_q[(size_t)M_ * D_];
__device__ float g_k[(size_t)M_ * D_];
__device__ float g_v[(size_t)M_ * D_];
__device__ float g_att[(size_t)M_ * D_];

// ---------------------------------------------------------------------------
// tf32 helpers
// ---------------------------------------------------------------------------
__device__ __forceinline__ uint32_t f2tf32(float x) {
    uint32_t y;
    asm("cvt.rna.tf32.f32 %0, %1;" : "=r"(y) : "f"(x));
    return y;
}

__device__ __forceinline__ void mma_tf32(float c[4],
                                         uint32_t a0, uint32_t a1,
                                         uint32_t a2, uint32_t a3,
                                         uint32_t b0, uint32_t b1) {
    asm volatile(
        "mma.sync.aligned.m16n8k8.row.col.f32.tf32.tf32.f32 "
        "{%0,%1,%2,%3}, {%4,%5,%6,%7}, {%8,%9}, {%0,%1,%2,%3};\n"
        : "+f"(c[0]), "+f"(c[1]), "+f"(c[2]), "+f"(c[3])
        : "r"(a0), "r"(a1), "r"(a2), "r"(a3), "r"(b0), "r"(b1));
}

// ---------------------------------------------------------------------------
// tf32 tensor-core GEMM tile: C[m,n] = sum_k A[m,k] * B[n,k]
// A: MxK row-major fp32, B: NxK row-major fp32 (i.e. C = A @ B^T).
// Block: 128x128 tile, 256 threads = 8 warps (2 m-warps x 4 n-warps),
// warp tile 64x32, BK=32. fp32 -> tf32 (rna) at smem store.
// (R3-measured: 77us, tensor=41%)
// ---------------------------------------------------------------------------
#define BK_ 32
#define SPAD_ 36   // smem row stride in floats (32 + 4 pad)

__device__ __forceinline__ void gemm_tf32_tile(
    const float* __restrict__ A, const float* __restrict__ Bm,
    float* __restrict__ C, int brow, int bcol)
{
    const int K = D_;
    const int N = D_;

    __shared__ uint32_t As[128 * SPAD_];
    __shared__ uint32_t Bs[128 * SPAD_];

    const int tid = threadIdx.x;
    const int wid = tid >> 5;
    const int lane = tid & 31;
    const int gid = lane >> 2;      // groupID 0..7
    const int tig = lane & 3;       // thread-in-group 0..3

    const int wm = wid >> 2;        // 0..1  (m-warp)
    const int wn = wid & 3;         // 0..3  (n-warp)

    float acc[4][4][4];             // [mt][nt][4]
#pragma unroll
    for (int mt = 0; mt < 4; mt++)
#pragma unroll
        for (int nt = 0; nt < 4; nt++)
#pragma unroll
            for (int r = 0; r < 4; r++) acc[mt][nt][r] = 0.0f;

    for (int k0 = 0; k0 < K; k0 += BK_) {
        // cooperative load: 128 rows x 32 cols each of A and B = 1024 float4
#pragma unroll
        for (int i = 0; i < 4; i++) {
            int li = i * 256 + tid;
            int row = li >> 3;
            int c4 = (li & 7) << 2;
            float4 a4 = *(const float4*)(A + (size_t)(brow + row) * K + k0 + c4);
            float4 b4 = *(const float4*)(Bm + (size_t)(bcol + row) * K + k0 + c4);
            uint32_t* ap = &As[row * SPAD_ + c4];
            ap[0] = f2tf32(a4.x); ap[1] = f2tf32(a4.y);
            ap[2] = f2tf32(a4.z); ap[3] = f2tf32(a4.w);
            uint32_t* bp = &Bs[row * SPAD_ + c4];
            bp[0] = f2tf32(b4.x); bp[1] = f2tf32(b4.y);
            bp[2] = f2tf32(b4.z); bp[3] = f2tf32(b4.w);
        }
        __syncthreads();

#pragma unroll
        for (int ka = 0; ka < 4; ka++) {
            const int kc = ka * 8 + tig;
            uint32_t af[4][4];
#pragma unroll
            for (int mt = 0; mt < 4; mt++) {
                int r0 = wm * 64 + mt * 16 + gid;
                af[mt][0] = As[r0 * SPAD_ + kc];
                af[mt][1] = As[(r0 + 8) * SPAD_ + kc];
                af[mt][2] = As[r0 * SPAD_ + kc + 4];
                af[mt][3] = As[(r0 + 8) * SPAD_ + kc + 4];
            }
            uint32_t bf[4][2];
#pragma unroll
            for (int nt = 0; nt < 4; nt++) {
                int rn = wn * 32 + nt * 8 + gid;
                bf[nt][0] = Bs[rn * SPAD_ + kc];
                bf[nt][1] = Bs[rn * SPAD_ + kc + 4];
            }
#pragma unroll
            for (int mt = 0; mt < 4; mt++)
#pragma unroll
                for (int nt = 0; nt < 4; nt++)
                    mma_tf32(acc[mt][nt],
                             af[mt][0], af[mt][1], af[mt][2], af[mt][3],
                             bf[nt][0], bf[nt][1]);
        }
        __syncthreads();
    }

#pragma unroll
    for (int mt = 0; mt < 4; mt++) {
        int row = brow + wm * 64 + mt * 16 + gid;
#pragma unroll
        for (int nt = 0; nt < 4; nt++) {
            int col = bcol + wn * 32 + nt * 8 + tig * 2;
            *(float2*)(C + (size_t)row * N + col) =
                make_float2(acc[mt][nt][0], acc[mt][nt][1]);
            *(float2*)(C + (size_t)(row + 8) * N + col) =
                make_float2(acc[mt][nt][2], acc[mt][nt][3]);
        }
    }
}

__global__ __launch_bounds__(256) void qkv_proj_kernel(
    const float* __restrict__ x,
    const float* __restrict__ wq,
    const float* __restrict__ wk,
    const float* __restrict__ wv)
{
    const float* w;
    float* dst;
    switch (blockIdx.z) {
        case 0:  w = wq; dst = g_q; break;
        case 1:  w = wk; dst = g_k; break;
        default: w = wv; dst = g_v; break;
    }
    gemm_tf32_tile(x, w, dst, blockIdx.y * 128, blockIdx.x * 128);
}

__global__ __launch_bounds__(256) void out_proj_kernel(
    const float* __restrict__ wo, float* __restrict__ out)
{
    gemm_tf32_tile(g_att, wo, out, blockIdx.y * 128, blockIdx.x * 128);
}

// ---------------------------------------------------------------------------
// RoPE on g_q and g_k in-place.
// ---------------------------------------------------------------------------
__global__ void rope_kernel(const int* __restrict__ pos)
{
    const int PAIRS = M_ * D_ / 2;
    int idx = blockIdx.x * blockDim.x + threadIdx.x;
    if (idx >= PAIRS) return;

    int c2  = idx % (D_ / 2);
    int row = idx / (D_ / 2);
    int s   = row & (S_ - 1);
    int kk  = c2 & (DH_ / 2 - 1);

    const float l2t_over = 13.287712379549449f / 32.0f;  // log2(10000)/32
    float inv = exp2f(-(float)kk * l2t_over);
    float ang = (float)pos[s] * inv;
    float sn, cs;
    sincosf(ang, &sn, &cs);

    size_t off = (size_t)row * D_ + 2 * c2;
    float qe = g_q[off], qo = g_q[off + 1];
    g_q[off]     = cs * qe - sn * qo;
    g_q[off + 1] = sn * qe + cs * qo;
    float ke = g_k[off], ko = g_k[off + 1];
    g_k[off]     = cs * ke - sn * ko;
    g_k[off + 1] = sn * ke + cs * ko;
}

// ---------------------------------------------------------------------------
// Causal flash attention with tf32 mma (R4-measured good).
// Grid (S/128, H, B), block 256 (8 warps). Warp w owns q-rows [16w,16w+16).
// ---------------------------------------------------------------------------
#define PADV 72
#define PADP 36

__global__ __launch_bounds__(256) void attn_mma_kernel()
{
    __shared__ uint32_t Kt[64 * 32];          // 8 KB
    __shared__ uint32_t Vs[32 * PADV];        // 9 KB
    __shared__ uint32_t Ps[8][16 * PADP];     // 18 KB

    const int b   = blockIdx.z;
    const int h   = blockIdx.y;
    const int q0  = blockIdx.x * 128;
    const int tid = threadIdx.x;
    const int w   = tid >> 5;
    const int lane = tid & 31;
    const int gid = lane >> 2;
    const int tig = lane & 3;

    const int r0 = q0 + 16 * w + gid;       // first owned row (second = r0+8)

    // Q fragments (scaled by 1/sqrt(dh) = 0.125, exact power of 2)
    uint32_t qf[8][4];
    {
        const float* Qb = g_q + ((size_t)(b * S_) + r0) * D_ + h * DH_;
#pragma unroll
        for (int kst = 0; kst < 8; kst++) {
            qf[kst][0] = f2tf32(Qb[kst * 8 + tig] * 0.125f);
            qf[kst][1] = f2tf32(Qb[8 * D_ + kst * 8 + tig] * 0.125f);
            qf[kst][2] = f2tf32(Qb[kst * 8 + tig + 4] * 0.125f);
            qf[kst][3] = f2tf32(Qb[8 * D_ + kst * 8 + tig + 4] * 0.125f);
        }
    }

    float o[8][4];
#pragma unroll
    for (int nb = 0; nb < 8; nb++)
#pragma unroll
        for (int r = 0; r < 4; r++) o[nb][r] = 0.0f;
    float m0 = -1e30f, m1 = -1e30f, l0 = 0.0f, l1 = 0.0f;

    const int ntiles  = (q0 + 128) / 32;
    const int wminrow = q0 + 16 * w;
    const int wmaxrow = wminrow + 15;

    for (int t = 0; t < ntiles; t++) {
        const int t0 = t * 32;

        // ---- load K tile transposed+swizzled: warp w covers dims [8w,8w+8) ----
        {
            const float* Kp = g_k + ((size_t)(b * S_) + t0 + lane) * D_ + h * DH_ + w * 8;
            float4 ka = *(const float4*)Kp;
            float4 kb = *(const float4*)(Kp + 4);
            float kv[8] = {ka.x, ka.y, ka.z, ka.w, kb.x, kb.y, kb.z, kb.w};
#pragma unroll
            for (int i = 0; i < 8; i++) {
                int d = w * 8 + i;
                Kt[d * 32 + (lane ^ (8 * (d & 3)))] = f2tf32(kv[i]);
            }
        }
        // ---- load V tile natural ----
        {
            int key  = tid >> 3;
            int part = tid & 7;
            const float* Vp = g_v + ((size_t)(b * S_) + t0 + key) * D_ + h * DH_ + part * 8;
            float4 va = *(const float4*)Vp;
            float4 vb = *(const float4*)(Vp + 4);
            *(uint4*)&Vs[key * PADV + part * 8] =
                make_uint4(f2tf32(va.x), f2tf32(va.y), f2tf32(va.z), f2tf32(va.w));
            *(uint4*)&Vs[key * PADV + part * 8 + 4] =
                make_uint4(f2tf32(vb.x), f2tf32(vb.y), f2tf32(vb.z), f2tf32(vb.w));
        }
        __syncthreads();

        if (t0 <= wmaxrow) {   // otherwise tile fully masked for this warp
            // ---- S = Q K^T (16 x 32 per warp) ----
            float s[4][4];
#pragma unroll
            for (int nb = 0; nb < 4; nb++)
#pragma unroll
                for (int r = 0; r < 4; r++) s[nb][r] = 0.0f;

#pragma unroll
            for (int kst = 0; kst < 8; kst++) {
#pragma unroll
                for (int nb = 0; nb < 4; nb++) {
                    uint32_t b0 = Kt[(kst * 8 + tig) * 32 + ((nb * 8 + gid) ^ (8 * tig))];
                    uint32_t b1 = Kt[(kst * 8 + tig + 4) * 32 + ((nb * 8 + gid) ^ (8 * tig))];
                    mma_tf32(s[nb], qf[kst][0], qf[kst][1], qf[kst][2], qf[kst][3], b0, b1);
                }
            }

            // ---- causal mask ----
            if (t0 + 31 > wminrow) {
#pragma unroll
                for (int nb = 0; nb < 4; nb++) {
                    int key = t0 + nb * 8 + 2 * tig;
                    if (key     > r0)     s[nb][0] = -1e30f;
                    if (key + 1 > r0)     s[nb][1] = -1e30f;
                    if (key     > r0 + 8) s[nb][2] = -1e30f;
                    if (key + 1 > r0 + 8) s[nb][3] = -1e30f;
                }
            }

            // ---- online softmax ----
            float mx0 = -1e30f, mx1 = -1e30f;
#pragma unroll
            for (int nb = 0; nb < 4; nb++) {
                mx0 = fmaxf(mx0, fmaxf(s[nb][0], s[nb][1]));
                mx1 = fmaxf(mx1, fmaxf(s[nb][2], s[nb][3]));
            }
            mx0 = fmaxf(mx0, __shfl_xor_sync(0xffffffffu, mx0, 1));
            mx0 = fmaxf(mx0, __shfl_xor_sync(0xffffffffu, mx0, 2));
            mx1 = fmaxf(mx1, __shfl_xor_sync(0xffffffffu, mx1, 1));
            mx1 = fmaxf(mx1, __shfl_xor_sync(0xffffffffu, mx1, 2));

            float mn0 = fmaxf(m0, mx0);
            float mn1 = fmaxf(m1, mx1);
            float a0 = __expf(m0 - mn0);
            float a1 = __expf(m1 - mn1);

            float ps0 = 0.0f, ps1 = 0.0f;
            uint32_t pt[4][4];
#pragma unroll
            for (int nb = 0; nb < 4; nb++) {
                float p0 = __expf(s[nb][0] - mn0);
                float p1 = __expf(s[nb][1] - mn0);
                float p2 = __expf(s[nb][2] - mn1);
                float p3 = __expf(s[nb][3] - mn1);
                ps0 += p0 + p1;
                ps1 += p2 + p3;
                pt[nb][0] = f2tf32(p0);
                pt[nb][1] = f2tf32(p1);
                pt[nb][2] = f2tf32(p2);
                pt[nb][3] = f2tf32(p3);
            }
            ps0 += __shfl_xor_sync(0xffffffffu, ps0, 1);
            ps0 += __shfl_xor_sync(0xffffffffu, ps0, 2);
            ps1 += __shfl_xor_sync(0xffffffffu, ps1, 1);
            ps1 += __shfl_xor_sync(0xffffffffu, ps1, 2);

            l0 = l0 * a0 + ps0;
            l1 = l1 * a1 + ps1;
            m0 = mn0;
            m1 = mn1;

#pragma unroll
            for (int nb = 0; nb < 8; nb++) {
                o[nb][0] *= a0;
                o[nb][1] *= a0;
                o[nb][2] *= a1;
                o[nb][3] *= a1;
            }

            // ---- P -> per-warp smem (A-fragment layout conversion) ----
            uint32_t* pw = &Ps[w][0];
#pragma unroll
            for (int nb = 0; nb < 4; nb++) {
                *(uint2*)&pw[gid * PADP + nb * 8 + 2 * tig] =
                    make_uint2(pt[nb][0], pt[nb][1]);
                *(uint2*)&pw[(gid + 8) * PADP + nb * 8 + 2 * tig] =
                    make_uint2(pt[nb][2], pt[nb][3]);
            }
            __syncwarp();

            // ---- O += P V ----
#pragma unroll
            for (int kst = 0; kst < 4; kst++) {
                uint32_t pa0 = pw[gid * PADP + kst * 8 + tig];
                uint32_t pa1 = pw[(gid + 8) * PADP + kst * 8 + tig];
                uint32_t pa2 = pw[gid * PADP + kst * 8 + tig + 4];
                uint32_t pa3 = pw[(gid + 8) * PADP + kst * 8 + tig + 4];
#pragma unroll
                for (int nb = 0; nb < 8; nb++) {
                    uint32_t b0 = Vs[(kst * 8 + tig) * PADV + nb * 8 + gid];
                    uint32_t b1 = Vs[(kst * 8 + tig + 4) * PADV + nb * 8 + gid];
                    mma_tf32(o[nb], pa0, pa1, pa2, pa3, b0, b1);
                }
            }
            __syncwarp();
        }
        __syncthreads();
    }

    // ---- epilogue ----
    float inv0 = 1.0f / l0;
    float inv1 = 1.0f / l1;
    float* Ob = g_att + ((size_t)(b * S_) + r0) * D_ + h * DH_;
#pragma unroll
    for (int nb = 0; nb < 8; nb++) {
        *(float2*)&Ob[nb * 8 + 2 * tig] =
            make_float2(o[nb][0] * inv0, o[nb][1] * inv0);
        *(float2*)&Ob[8 * D_ + nb * 8 + 2 * tig] =
            make_float2(o[nb][2] * inv1, o[nb][3] * inv1);
    }
}

// ---------------------------------------------------------------------------
// kernel_launch — launches ONLY (graph-capture safe)
// Inputs: x, q_proj_weight, k_proj_weight, v_proj_weight, o_proj_weight,
//         token_positions
// ---------------------------------------------------------------------------
extern "C" void kernel_launch(void* const* d_in, const int* in_sizes, int n_in,
                              void* d_out, int out_size)
{
    const float* x   = (const float*)d_in[0];
    const float* wq  = (const float*)d_in[1];
    const float* wk  = (const float*)d_in[2];
    const float* wv  = (const float*)d_in[3];
    const float* wo  = (const float*)d_in[4];
    const int*   pos = (const int*)d_in[5];
    float* out = (float*)d_out;

    dim3 qkvGrid(D_ / 128, M_ / 128, 3);   // (8, 32, 3)
    qkv_proj_kernel<<<qkvGrid, 256>>>(x, wq, wk, wv);

    const int PAIRS = M_ * D_ / 2;
    rope_kernel<<<(PAIRS + 255) / 256, 256>>>(pos);

    dim3 attnGrid(S_ / 128, H_, B_);       // (16, 16, 2)
    attn_mma_kernel<<<attnGrid, 256>>>();

    dim3 gemmGrid(D_ / 128, M_ / 128);     // (8, 32)
    out_proj_kernel<<<gemmGrid, 256>>>(wo, out);
}